// round 8
// baseline (speedup 1.0000x reference)
#include <cuda_runtime.h>
#include <math.h>

// GRU: T=512, B=1024, H=128 (fp32).
// Fused persistent kernel: 128 blocks x 384 threads, 8 batch rows per block.
// w_hh resident in SMEM (transposed [k][g]); w_ih streamed from L2 (transposed).
// h kept in SMEM across all 512 steps; output projection fused at the end.

#define TT 512
#define BB 1024
#define HH 128
#define GG 384            // 3*H
#define ROWS 8
#define NTHREADS 384
#define NBLOCKS (BB / ROWS)   // 128

// Transposed weights, [k][g] layout (k = input dim 0..127, g = gate dim 0..383)
__device__ float g_wiht[GG * HH];
__device__ float g_whht[GG * HH];

// SMEM partition (floats):
//  whh_s : GG*HH      = 49152   (192 KB)
//  h_s   : HH*ROWS    = 1024    ([k][r])
//  x_s   : HH*ROWS    = 1024    ([k][r])
//  pre_s : GG*ROWS    = 3072    (pre-activations; g<256: xg+hg, g>=256: xn only)
//  hn_s  : HH*ROWS    = 1024    (hn part for n-gate)
//  bih_s : GG
//  bhh_s : GG
#define SMEM_FLOATS (GG*HH + 2*HH*ROWS + GG*ROWS + HH*ROWS + 2*GG)
#define SMEM_BYTES  (SMEM_FLOATS * 4)   // 224,256 bytes

__global__ void transpose_weights_kernel(const float* __restrict__ wih,
                                         const float* __restrict__ whh) {
    int idx = blockIdx.x * blockDim.x + threadIdx.x;
    if (idx < GG * HH) {
        int g = idx / HH;
        int k = idx - g * HH;
        g_wiht[k * GG + g] = wih[idx];
        g_whht[k * GG + g] = whh[idx];
    }
}

extern __shared__ float smem[];

__global__ void __launch_bounds__(NTHREADS, 1)
gru_persistent_kernel(const float* __restrict__ x,
                      const float* __restrict__ h0,
                      const float* __restrict__ b_ih,
                      const float* __restrict__ b_hh,
                      const float* __restrict__ w_out,
                      const float* __restrict__ b_out,
                      float* __restrict__ out) {
    float* whh_s = smem;
    float* h_s   = whh_s + GG * HH;
    float* x_s   = h_s + HH * ROWS;
    float* pre_s = x_s + HH * ROWS;
    float* hn_s  = pre_s + GG * ROWS;
    float* bih_s = hn_s + HH * ROWS;
    float* bhh_s = bih_s + GG;

    const int tid = threadIdx.x;
    const int b0  = blockIdx.x * ROWS;

    // Load transposed w_hh into SMEM (coalesced read, linear write).
    for (int i = tid; i < GG * HH; i += NTHREADS) whh_s[i] = g_whht[i];
    for (int i = tid; i < GG; i += NTHREADS) { bih_s[i] = b_ih[i]; bhh_s[i] = b_hh[i]; }

    // Load h0 and x[t=0] into [k][r] layout (contiguous global reads).
    for (int j = tid; j < HH * ROWS; j += NTHREADS) {
        int r = j >> 7;          // j / 128
        int i = j & (HH - 1);    // j % 128
        h_s[i * ROWS + r] = h0[b0 * HH + j];
        x_s[i * ROWS + r] = x[b0 * HH + j];
    }
    __syncthreads();

    const int g = tid;                    // one thread per gate dim
    const float bx = bih_s[g];
    const float bh = bhh_s[g];
    const float4* h4 = (const float4*)h_s;
    const float4* x4 = (const float4*)x_s;
    const float* wi_base = g_wiht + g;    // stride GG per k
    const float* wh_base = whh_s + g;

    for (int t = 0; t < TT; ++t) {
        __syncthreads();  // A: h_s and x_s for step t are ready

        float ax[ROWS], ah[ROWS];
        #pragma unroll
        for (int r = 0; r < ROWS; ++r) { ax[r] = bx; ah[r] = bh; }

        #pragma unroll 4
        for (int k = 0; k < HH; ++k) {
            float wiv = wi_base[k * GG];      // L2 (coalesced across lanes)
            float whv = wh_base[k * GG];      // SMEM (conflict-free)
            float4 xa = x4[2 * k];
            float4 xb = x4[2 * k + 1];
            float4 ha = h4[2 * k];
            float4 hb = h4[2 * k + 1];
            ax[0] += wiv * xa.x;  ax[1] += wiv * xa.y;
            ax[2] += wiv * xa.z;  ax[3] += wiv * xa.w;
            ax[4] += wiv * xb.x;  ax[5] += wiv * xb.y;
            ax[6] += wiv * xb.z;  ax[7] += wiv * xb.w;
            ah[0] += whv * ha.x;  ah[1] += whv * ha.y;
            ah[2] += whv * ha.z;  ah[3] += whv * ha.w;
            ah[4] += whv * hb.x;  ah[5] += whv * hb.y;
            ah[6] += whv * hb.z;  ah[7] += whv * hb.w;
        }

        // Publish pre-activations.
        float* pg = pre_s + g * ROWS;
        if (g < 2 * HH) {
            // r / z gates: only the sum is needed
            #pragma unroll
            for (int r = 0; r < ROWS; ++r) pg[r] = ax[r] + ah[r];
        } else {
            // n gate: xn and hn must stay separate (n = tanh(xn + r*hn))
            float* hg = hn_s + (g - 2 * HH) * ROWS;
            #pragma unroll
            for (int r = 0; r < ROWS; ++r) { pg[r] = ax[r]; hg[r] = ah[r]; }
        }

        __syncthreads();  // B: pre_s/hn_s ready; x_s free for refill

        // Prefetch x for t+1 (x_s reads of step t finished at barrier B).
        if (t + 1 < TT) {
            const float* xt = x + (size_t)(t + 1) * BB * HH + b0 * HH;
            for (int j = tid; j < HH * ROWS; j += NTHREADS) {
                int r = j >> 7;
                int i = j & (HH - 1);
                x_s[i * ROWS + r] = xt[j];
            }
        }

        // Gate combine + h update (1024 items, each touched by exactly one thread).
        for (int m = tid; m < HH * ROWS; m += NTHREADS) {
            int i  = m >> 3;
            int rr = m & 7;
            float a_r = pre_s[i * ROWS + rr];
            float a_z = pre_s[(HH + i) * ROWS + rr];
            float xn  = pre_s[(2 * HH + i) * ROWS + rr];
            float hn  = hn_s[i * ROWS + rr];
            float rg = 1.0f / (1.0f + expf(-a_r));
            float zg = 1.0f / (1.0f + expf(-a_z));
            float nn = tanhf(xn + rg * hn);
            float hv = h_s[i * ROWS + rr];
            h_s[i * ROWS + rr] = (1.0f - zg) * nn + zg * hv;
        }
    }

    __syncthreads();

    // Output projection: out[b] = h[b] . w_out + b_out  (one warp per row)
    int warp = tid >> 5;
    int lane = tid & 31;
    if (warp < ROWS) {
        float s = 0.0f;
        for (int i = lane; i < HH; i += 32) s += h_s[i * ROWS + warp] * w_out[i];
        #pragma unroll
        for (int o = 16; o > 0; o >>= 1) s += __shfl_down_sync(0xffffffffu, s, o);
        if (lane == 0) out[b0 + warp] = s + b_out[0];
    }
}

extern "C" void kernel_launch(void* const* d_in, const int* in_sizes, int n_in,
                              void* d_out, int out_size) {
    const float* x    = (const float*)d_in[0];
    const float* h0   = (const float*)d_in[1];
    const float* wih  = (const float*)d_in[2];
    const float* whh  = (const float*)d_in[3];
    const float* bih  = (const float*)d_in[4];
    const float* bhh  = (const float*)d_in[5];
    const float* wout = (const float*)d_in[6];
    const float* bout = (const float*)d_in[7];
    float* out = (float*)d_out;

    cudaFuncSetAttribute(gru_persistent_kernel,
                         cudaFuncAttributeMaxDynamicSharedMemorySize, SMEM_BYTES);

    transpose_weights_kernel<<<(GG * HH + 255) / 256, 256>>>(wih, whh);
    gru_persistent_kernel<<<NBLOCKS, NTHREADS, SMEM_BYTES>>>(
        x, h0, bih, bhh, wout, bout, out);
}

// round 10
// speedup vs baseline: 1.0096x; 1.0096x over previous
#include <cuda_runtime.h>
#include <math.h>

// GRU: T=512, B=1024, H=128 (fp32).
// Persistent fused kernel, 128 blocks x 384 threads, 8 batch rows per block.
// R9: f32x2 packed FMAs (row pairs), wiv L2-prefetch ring, fast-math tail.

#define TT 512
#define BB 1024
#define HH 128
#define GG 384            // 3*H
#define ROWS 8
#define NTHREADS 384
#define NBLOCKS (BB / ROWS)   // 128

// Transposed weights, [k][g] layout (k = input dim 0..127, g = gate dim 0..383)
__device__ float g_wiht[GG * HH];
__device__ float g_whht[GG * HH];

#define SMEM_FLOATS (GG*HH + 2*HH*ROWS + GG*ROWS + HH*ROWS + 2*GG)
#define SMEM_BYTES  (SMEM_FLOATS * 4)   // 224,256 bytes

typedef unsigned long long u64t;

__device__ __forceinline__ u64t pack2(float a, float b) {
    u64t r;
    asm("mov.b64 %0, {%1, %2};" : "=l"(r) : "f"(a), "f"(b));
    return r;
}
__device__ __forceinline__ u64t fma2(u64t a, u64t b, u64t c) {
    u64t d;
    asm("fma.rn.f32x2 %0, %1, %2, %3;" : "=l"(d) : "l"(a), "l"(b), "l"(c));
    return d;
}
__device__ __forceinline__ u64t add2(u64t a, u64t b) {
    u64t d;
    asm("add.rn.f32x2 %0, %1, %2;" : "=l"(d) : "l"(a), "l"(b));
    return d;
}
__device__ __forceinline__ float sigmoid_fast(float x) {
    return 1.0f / (1.0f + __expf(-x));
}
__device__ __forceinline__ float tanh_fast(float x) {
    // 1 - 2/(e^{2x}+1); saturates correctly for |x| large (e -> inf or 0).
    float e = __expf(2.0f * x);
    return 1.0f - __fdividef(2.0f, e + 1.0f);
}

__global__ void transpose_weights_kernel(const float* __restrict__ wih,
                                         const float* __restrict__ whh) {
    int idx = blockIdx.x * blockDim.x + threadIdx.x;
    if (idx < GG * HH) {
        int g = idx / HH;
        int k = idx - g * HH;
        g_wiht[k * GG + g] = wih[idx];
        g_whht[k * GG + g] = whh[idx];
    }
}

extern __shared__ float smem[];

__global__ void __launch_bounds__(NTHREADS, 1)
gru_persistent_kernel(const float* __restrict__ x,
                      const float* __restrict__ h0,
                      const float* __restrict__ b_ih,
                      const float* __restrict__ b_hh,
                      const float* __restrict__ w_out,
                      const float* __restrict__ b_out,
                      float* __restrict__ out) {
    float* whh_s = smem;                  // [k][g] 49152 floats
    float* h_s   = whh_s + GG * HH;       // [k][r] 1024
    float* x_s   = h_s + HH * ROWS;       // [k][r] 1024
    float* pre_s = x_s + HH * ROWS;       // [g][r] 3072
    float* hn_s  = pre_s + GG * ROWS;     // [i][r] 1024
    float* bih_s = hn_s + HH * ROWS;
    float* bhh_s = bih_s + GG;

    const int tid = threadIdx.x;
    const int b0  = blockIdx.x * ROWS;

    for (int i = tid; i < GG * HH; i += NTHREADS) whh_s[i] = g_whht[i];
    for (int i = tid; i < GG; i += NTHREADS) { bih_s[i] = b_ih[i]; bhh_s[i] = b_hh[i]; }

    for (int j = tid; j < HH * ROWS; j += NTHREADS) {
        int r = j >> 7;
        int i = j & (HH - 1);
        h_s[i * ROWS + r] = h0[b0 * HH + j];
        x_s[i * ROWS + r] = x[b0 * HH + j];
    }
    __syncthreads();

    const int g = tid;
    const float bx = bih_s[g];
    const float bh = bhh_s[g];
    const u64t bx2 = pack2(bx, bx);
    const u64t bh2 = pack2(bh, bh);
    // Row-pair packed views of the [k][r] tiles (16B-aligned).
    const ulonglong2* x2v = (const ulonglong2*)x_s;
    const ulonglong2* h2v = (const ulonglong2*)h_s;
    const float* wi_base = g_wiht + g;    // stride GG per k (L2)
    const float* wh_base = whh_s + g;     // stride GG per k (SMEM)

    for (int t = 0; t < TT; ++t) {
        __syncthreads();  // A: h_s / x_s for step t ready

        u64t acx[4], ach[4];
        #pragma unroll
        for (int i = 0; i < 4; ++i) { acx[i] = bx2; ach[i] = bh2; }

        // wiv prefetch ring: 8 L2 loads in flight ahead of the consuming chunk.
        float wibuf[8];
        #pragma unroll
        for (int j = 0; j < 8; ++j) wibuf[j] = wi_base[j * GG];

        for (int kc = 0; kc < HH; kc += 8) {
            float winext[8];
            if (kc + 8 < HH) {
                #pragma unroll
                for (int j = 0; j < 8; ++j) winext[j] = wi_base[(kc + 8 + j) * GG];
            }
            #pragma unroll
            for (int j = 0; j < 8; ++j) {
                const int k = kc + j;
                const u64t wi2 = pack2(wibuf[j], wibuf[j]);
                const float whv = wh_base[k * GG];
                const u64t wh2 = pack2(whv, whv);
                const ulonglong2 xa = x2v[2 * k];
                const ulonglong2 xb = x2v[2 * k + 1];
                const ulonglong2 ha = h2v[2 * k];
                const ulonglong2 hb = h2v[2 * k + 1];
                acx[0] = fma2(wi2, xa.x, acx[0]);
                acx[1] = fma2(wi2, xa.y, acx[1]);
                acx[2] = fma2(wi2, xb.x, acx[2]);
                acx[3] = fma2(wi2, xb.y, acx[3]);
                ach[0] = fma2(wh2, ha.x, ach[0]);
                ach[1] = fma2(wh2, ha.y, ach[1]);
                ach[2] = fma2(wh2, hb.x, ach[2]);
                ach[3] = fma2(wh2, hb.y, ach[3]);
            }
            #pragma unroll
            for (int j = 0; j < 8; ++j) wibuf[j] = winext[j];
        }

        // Publish pre-activations (packed 64-bit stores, same [g][r] layout).
        if (g < 2 * HH) {
            u64t* pg = (u64t*)(pre_s + g * ROWS);
            #pragma unroll
            for (int i = 0; i < 4; ++i) pg[i] = add2(acx[i], ach[i]);
        } else {
            u64t* pg = (u64t*)(pre_s + g * ROWS);
            u64t* hg = (u64t*)(hn_s + (g - 2 * HH) * ROWS);
            #pragma unroll
            for (int i = 0; i < 4; ++i) { pg[i] = acx[i]; hg[i] = ach[i]; }
        }

        __syncthreads();  // B: pre_s/hn_s ready; x_s free for refill

        if (t + 1 < TT) {
            const float* xt = x + (size_t)(t + 1) * BB * HH + b0 * HH;
            for (int j = tid; j < HH * ROWS; j += NTHREADS) {
                int r = j >> 7;
                int i = j & (HH - 1);
                x_s[i * ROWS + r] = xt[j];
            }
        }

        // Gate combine + h update.
        for (int m = tid; m < HH * ROWS; m += NTHREADS) {
            int i  = m >> 3;
            int rr = m & 7;
            float a_r = pre_s[i * ROWS + rr];
            float a_z = pre_s[(HH + i) * ROWS + rr];
            float xn  = pre_s[(2 * HH + i) * ROWS + rr];
            float hn  = hn_s[i * ROWS + rr];
            float rg = sigmoid_fast(a_r);
            float zg = sigmoid_fast(a_z);
            float nn = tanh_fast(xn + rg * hn);
            float hv = h_s[i * ROWS + rr];
            h_s[i * ROWS + rr] = (1.0f - zg) * nn + zg * hv;
        }
    }

    __syncthreads();

    // Output projection: out[b] = h[b] . w_out + b_out (one warp per row)
    int warp = tid >> 5;
    int lane = tid & 31;
    if (warp < ROWS) {
        float s = 0.0f;
        for (int i = lane; i < HH; i += 32) s += h_s[i * ROWS + warp] * w_out[i];
        #pragma unroll
        for (int o = 16; o > 0; o >>= 1) s += __shfl_down_sync(0xffffffffu, s, o);
        if (lane == 0) out[b0 + warp] = s + b_out[0];
    }
}

extern "C" void kernel_launch(void* const* d_in, const int* in_sizes, int n_in,
                              void* d_out, int out_size) {
    const float* x    = (const float*)d_in[0];
    const float* h0   = (const float*)d_in[1];
    const float* wih  = (const float*)d_in[2];
    const float* whh  = (const float*)d_in[3];
    const float* bih  = (const float*)d_in[4];
    const float* bhh  = (const float*)d_in[5];
    const float* wout = (const float*)d_in[6];
    const float* bout = (const float*)d_in[7];
    float* out = (float*)d_out;

    cudaFuncSetAttribute(gru_persistent_kernel,
                         cudaFuncAttributeMaxDynamicSharedMemorySize, SMEM_BYTES);

    transpose_weights_kernel<<<(GG * HH + 255) / 256, 256>>>(wih, whh);
    gru_persistent_kernel<<<NBLOCKS, NTHREADS, SMEM_BYTES>>>(
        x, h0, bih, bhh, wout, bout, out);
}

// round 11
// speedup vs baseline: 1.0423x; 1.0324x over previous
#include <cuda_runtime.h>
#include <math.h>

// GRU: T=512, B=1024, H=128 (fp32).
// Persistent fused kernel, 128 blocks x 384 threads, 8 batch rows per block.
// R9: f32x2 packed FMAs (row pairs), wiv L2-prefetch ring.
// R11: MUFU-diet tail — tanh.approx.f32 everywhere, sigmoid via tanh identity
//      (6 MUFU/item -> 3 MUFU/item; MUFU was the hidden binding pipe).

#define TT 512
#define BB 1024
#define HH 128
#define GG 384            // 3*H
#define ROWS 8
#define NTHREADS 384
#define NBLOCKS (BB / ROWS)   // 128

// Transposed weights, [k][g] layout (k = input dim 0..127, g = gate dim 0..383)
__device__ float g_wiht[GG * HH];
__device__ float g_whht[GG * HH];

#define SMEM_FLOATS (GG*HH + 2*HH*ROWS + GG*ROWS + HH*ROWS + 2*GG)
#define SMEM_BYTES  (SMEM_FLOATS * 4)   // 224,256 bytes

typedef unsigned long long u64t;

__device__ __forceinline__ u64t pack2(float a, float b) {
    u64t r;
    asm("mov.b64 %0, {%1, %2};" : "=l"(r) : "f"(a), "f"(b));
    return r;
}
__device__ __forceinline__ u64t fma2(u64t a, u64t b, u64t c) {
    u64t d;
    asm("fma.rn.f32x2 %0, %1, %2, %3;" : "=l"(d) : "l"(a), "l"(b), "l"(c));
    return d;
}
__device__ __forceinline__ u64t add2(u64t a, u64t b) {
    u64t d;
    asm("add.rn.f32x2 %0, %1, %2;" : "=l"(d) : "l"(a), "l"(b));
    return d;
}
// Single-MUFU tanh (MUFU.TANH, sm_75+).
__device__ __forceinline__ float tanh_ptx(float x) {
    float y;
    asm("tanh.approx.f32 %0, %1;" : "=f"(y) : "f"(x));
    return y;
}
// sigmoid(x) = 0.5*tanh(x/2) + 0.5  -> 1 MUFU + 2 FMA (no division).
__device__ __forceinline__ float sigmoid_t(float x) {
    return fmaf(tanh_ptx(0.5f * x), 0.5f, 0.5f);
}

__global__ void transpose_weights_kernel(const float* __restrict__ wih,
                                         const float* __restrict__ whh) {
    int idx = blockIdx.x * blockDim.x + threadIdx.x;
    if (idx < GG * HH) {
        int g = idx / HH;
        int k = idx - g * HH;
        g_wiht[k * GG + g] = wih[idx];
        g_whht[k * GG + g] = whh[idx];
    }
}

extern __shared__ float smem[];

__global__ void __launch_bounds__(NTHREADS, 1)
gru_persistent_kernel(const float* __restrict__ x,
                      const float* __restrict__ h0,
                      const float* __restrict__ b_ih,
                      const float* __restrict__ b_hh,
                      const float* __restrict__ w_out,
                      const float* __restrict__ b_out,
                      float* __restrict__ out) {
    float* whh_s = smem;                  // [k][g] 49152 floats
    float* h_s   = whh_s + GG * HH;       // [k][r] 1024
    float* x_s   = h_s + HH * ROWS;       // [k][r] 1024
    float* pre_s = x_s + HH * ROWS;       // [g][r] 3072
    float* hn_s  = pre_s + GG * ROWS;     // [i][r] 1024
    float* bih_s = hn_s + HH * ROWS;
    float* bhh_s = bih_s + GG;

    const int tid = threadIdx.x;
    const int b0  = blockIdx.x * ROWS;

    for (int i = tid; i < GG * HH; i += NTHREADS) whh_s[i] = g_whht[i];
    for (int i = tid; i < GG; i += NTHREADS) { bih_s[i] = b_ih[i]; bhh_s[i] = b_hh[i]; }

    for (int j = tid; j < HH * ROWS; j += NTHREADS) {
        int r = j >> 7;
        int i = j & (HH - 1);
        h_s[i * ROWS + r] = h0[b0 * HH + j];
        x_s[i * ROWS + r] = x[b0 * HH + j];
    }
    __syncthreads();

    const int g = tid;
    const float bx = bih_s[g];
    const float bh = bhh_s[g];
    const u64t bx2 = pack2(bx, bx);
    const u64t bh2 = pack2(bh, bh);
    // Row-pair packed views of the [k][r] tiles (16B-aligned).
    const ulonglong2* x2v = (const ulonglong2*)x_s;
    const ulonglong2* h2v = (const ulonglong2*)h_s;
    const float* wi_base = g_wiht + g;    // stride GG per k (L2)
    const float* wh_base = whh_s + g;     // stride GG per k (SMEM)

    for (int t = 0; t < TT; ++t) {
        __syncthreads();  // A: h_s / x_s for step t ready

        u64t acx[4], ach[4];
        #pragma unroll
        for (int i = 0; i < 4; ++i) { acx[i] = bx2; ach[i] = bh2; }

        // wiv prefetch ring: 8 L2 loads in flight ahead of the consuming chunk.
        float wibuf[8];
        #pragma unroll
        for (int j = 0; j < 8; ++j) wibuf[j] = wi_base[j * GG];

        for (int kc = 0; kc < HH; kc += 8) {
            float winext[8];
            if (kc + 8 < HH) {
                #pragma unroll
                for (int j = 0; j < 8; ++j) winext[j] = wi_base[(kc + 8 + j) * GG];
            }
            #pragma unroll
            for (int j = 0; j < 8; ++j) {
                const int k = kc + j;
                const u64t wi2 = pack2(wibuf[j], wibuf[j]);
                const float whv = wh_base[k * GG];
                const u64t wh2 = pack2(whv, whv);
                const ulonglong2 xa = x2v[2 * k];
                const ulonglong2 xb = x2v[2 * k + 1];
                const ulonglong2 ha = h2v[2 * k];
                const ulonglong2 hb = h2v[2 * k + 1];
                acx[0] = fma2(wi2, xa.x, acx[0]);
                acx[1] = fma2(wi2, xa.y, acx[1]);
                acx[2] = fma2(wi2, xb.x, acx[2]);
                acx[3] = fma2(wi2, xb.y, acx[3]);
                ach[0] = fma2(wh2, ha.x, ach[0]);
                ach[1] = fma2(wh2, ha.y, ach[1]);
                ach[2] = fma2(wh2, hb.x, ach[2]);
                ach[3] = fma2(wh2, hb.y, ach[3]);
            }
            if (kc + 8 < HH) {
                #pragma unroll
                for (int j = 0; j < 8; ++j) wibuf[j] = winext[j];
            }
        }

        // Publish pre-activations (packed 64-bit stores, same [g][r] layout).
        if (g < 2 * HH) {
            u64t* pg = (u64t*)(pre_s + g * ROWS);
            #pragma unroll
            for (int i = 0; i < 4; ++i) pg[i] = add2(acx[i], ach[i]);
        } else {
            u64t* pg = (u64t*)(pre_s + g * ROWS);
            u64t* hg = (u64t*)(hn_s + (g - 2 * HH) * ROWS);
            #pragma unroll
            for (int i = 0; i < 4; ++i) { pg[i] = acx[i]; hg[i] = ach[i]; }
        }

        __syncthreads();  // B: pre_s/hn_s ready; x_s free for refill

        if (t + 1 < TT) {
            const float* xt = x + (size_t)(t + 1) * BB * HH + b0 * HH;
            for (int j = tid; j < HH * ROWS; j += NTHREADS) {
                int r = j >> 7;
                int i = j & (HH - 1);
                x_s[i * ROWS + r] = xt[j];
            }
        }

        // Gate combine + h update (3 MUFU per item).
        for (int m = tid; m < HH * ROWS; m += NTHREADS) {
            int i  = m >> 3;
            int rr = m & 7;
            float a_r = pre_s[i * ROWS + rr];
            float a_z = pre_s[(HH + i) * ROWS + rr];
            float xn  = pre_s[(2 * HH + i) * ROWS + rr];
            float hn  = hn_s[i * ROWS + rr];
            float rg = sigmoid_t(a_r);
            float zg = sigmoid_t(a_z);
            float nn = tanh_ptx(fmaf(rg, hn, xn));
            float hv = h_s[i * ROWS + rr];
            h_s[i * ROWS + rr] = fmaf(zg, hv - nn, nn);   // (1-z)*n + z*h
        }
    }

    __syncthreads();

    // Output projection: out[b] = h[b] . w_out + b_out (one warp per row)
    int warp = tid >> 5;
    int lane = tid & 31;
    if (warp < ROWS) {
        float s = 0.0f;
        for (int i = lane; i < HH; i += 32) s += h_s[i * ROWS + warp] * w_out[i];
        #pragma unroll
        for (int o = 16; o > 0; o >>= 1) s += __shfl_down_sync(0xffffffffu, s, o);
        if (lane == 0) out[b0 + warp] = s + b_out[0];
    }
}

extern "C" void kernel_launch(void* const* d_in, const int* in_sizes, int n_in,
                              void* d_out, int out_size) {
    const float* x    = (const float*)d_in[0];
    const float* h0   = (const float*)d_in[1];
    const float* wih  = (const float*)d_in[2];
    const float* whh  = (const float*)d_in[3];
    const float* bih  = (const float*)d_in[4];
    const float* bhh  = (const float*)d_in[5];
    const float* wout = (const float*)d_in[6];
    const float* bout = (const float*)d_in[7];
    float* out = (float*)d_out;

    cudaFuncSetAttribute(gru_persistent_kernel,
                         cudaFuncAttributeMaxDynamicSharedMemorySize, SMEM_BYTES);

    transpose_weights_kernel<<<(GG * HH + 255) / 256, 256>>>(wih, whh);
    gru_persistent_kernel<<<NBLOCKS, NTHREADS, SMEM_BYTES>>>(
        x, h0, bih, bhh, wout, bout, out);
}

// round 14
// speedup vs baseline: 1.1191x; 1.0736x over previous
#include <cuda_runtime.h>
#include <math.h>

// GRU: T=512, B=1024, H=128 (fp32).
// R12: split-matrix warp doubling. 128 blocks x 768 threads.
//   warps 0-11  (part 0): h-GEMM only, whh from SMEM
//   warps 12-23 (part 1): x-GEMM only, w_ih streamed from L2 (prefetch ring)
// Partials in pre_h / pre_x SMEM buffers; tail combines. 2x warps per SMSP
// to hide LDS/L2/MUFU latency (profile showed latency-bound at 3 warps/SMSP).

#define TT 512
#define BB 1024
#define HH 128
#define GG 384            // 3*H
#define ROWS 8
#define NTHREADS 768
#define NBLOCKS (BB / ROWS)   // 128

__device__ float g_wiht[GG * HH];   // [k][g]
__device__ float g_whht[GG * HH];   // [k][g]

// SMEM (floats): whh_s 49152 | h_s 1024 | x_s 1024 | pre_x 3072 | pre_h 3072
#define SMEM_FLOATS (GG*HH + 2*HH*ROWS + 2*GG*ROWS)
#define SMEM_BYTES  (SMEM_FLOATS * 4)   // 229,376 bytes (<= 227KB opt-in)

typedef unsigned long long u64t;

__device__ __forceinline__ u64t pack2(float a, float b) {
    u64t r;
    asm("mov.b64 %0, {%1, %2};" : "=l"(r) : "f"(a), "f"(b));
    return r;
}
__device__ __forceinline__ u64t fma2(u64t a, u64t b, u64t c) {
    u64t d;
    asm("fma.rn.f32x2 %0, %1, %2, %3;" : "=l"(d) : "l"(a), "l"(b), "l"(c));
    return d;
}
__device__ __forceinline__ float tanh_ptx(float x) {
    float y;
    asm("tanh.approx.f32 %0, %1;" : "=f"(y) : "f"(x));
    return y;
}
__device__ __forceinline__ float sigmoid_t(float x) {
    return fmaf(tanh_ptx(0.5f * x), 0.5f, 0.5f);
}

__global__ void transpose_weights_kernel(const float* __restrict__ wih,
                                         const float* __restrict__ whh) {
    int idx = blockIdx.x * blockDim.x + threadIdx.x;
    if (idx < GG * HH) {
        int g = idx / HH;
        int k = idx - g * HH;
        g_wiht[k * GG + g] = wih[idx];
        g_whht[k * GG + g] = whh[idx];
    }
}

extern __shared__ float smem[];

__global__ void __launch_bounds__(NTHREADS, 1)
gru_persistent_kernel(const float* __restrict__ x,
                      const float* __restrict__ h0,
                      const float* __restrict__ b_ih,
                      const float* __restrict__ b_hh,
                      const float* __restrict__ w_out,
                      const float* __restrict__ b_out,
                      float* __restrict__ out) {
    float* whh_s = smem;                    // [k][g] 49152
    float* h_s   = whh_s + GG * HH;         // [k][r] 1024
    float* x_s   = h_s + HH * ROWS;         // [k][r] 1024
    float* pre_x = x_s + HH * ROWS;         // [g][r] 3072 (x-part, incl b_ih)
    float* pre_h = pre_x + GG * ROWS;       // [g][r] 3072 (h-part, incl b_hh)

    const int tid  = threadIdx.x;
    const int b0   = blockIdx.x * ROWS;
    const int part = tid / GG;              // 0: h-GEMM, 1: x-GEMM
    const int g    = tid - part * GG;

    for (int i = tid; i < GG * HH; i += NTHREADS) whh_s[i] = g_whht[i];

    for (int j = tid; j < HH * ROWS; j += NTHREADS) {
        int r = j >> 7;
        int i = j & (HH - 1);
        h_s[i * ROWS + r] = h0[b0 * HH + j];
        x_s[i * ROWS + r] = x[b0 * HH + j];
    }
    __syncthreads();

    // Per-thread bias (registers; folded into the accumulator init).
    const float bias = (part == 0) ? b_hh[g] : b_ih[g];
    const u64t bias2 = pack2(bias, bias);

    const ulonglong2* x2v = (const ulonglong2*)x_s;
    const ulonglong2* h2v = (const ulonglong2*)h_s;
    const float* wh_base = whh_s + g;       // SMEM, stride GG
    const float* wi_base = g_wiht + g;      // L2,   stride GG

    for (int t = 0; t < TT; ++t) {
        __syncthreads();  // A: h_s / x_s for step t ready

        u64t ac[4];
        #pragma unroll
        for (int i = 0; i < 4; ++i) ac[i] = bias2;

        if (part == 0) {
            // h-GEMM: all operands on-chip (SMEM).
            #pragma unroll 8
            for (int k = 0; k < HH; ++k) {
                const float whv = wh_base[k * GG];
                const u64t wh2 = pack2(whv, whv);
                const ulonglong2 ha = h2v[2 * k];
                const ulonglong2 hb = h2v[2 * k + 1];
                ac[0] = fma2(wh2, ha.x, ac[0]);
                ac[1] = fma2(wh2, ha.y, ac[1]);
                ac[2] = fma2(wh2, hb.x, ac[2]);
                ac[3] = fma2(wh2, hb.y, ac[3]);
            }
            u64t* pg = (u64t*)(pre_h + g * ROWS);
            #pragma unroll
            for (int i = 0; i < 4; ++i) pg[i] = ac[i];
        } else {
            // x-GEMM: weights from L2 with an 8-deep prefetch ring.
            float wibuf[8];
            #pragma unroll
            for (int j = 0; j < 8; ++j) wibuf[j] = wi_base[j * GG];

            for (int kc = 0; kc < HH; kc += 8) {
                float winext[8];
                if (kc + 8 < HH) {
                    #pragma unroll
                    for (int j = 0; j < 8; ++j) winext[j] = wi_base[(kc + 8 + j) * GG];
                }
                #pragma unroll
                for (int j = 0; j < 8; ++j) {
                    const int k = kc + j;
                    const u64t wi2 = pack2(wibuf[j], wibuf[j]);
                    const ulonglong2 xa = x2v[2 * k];
                    const ulonglong2 xb = x2v[2 * k + 1];
                    ac[0] = fma2(wi2, xa.x, ac[0]);
                    ac[1] = fma2(wi2, xa.y, ac[1]);
                    ac[2] = fma2(wi2, xb.x, ac[2]);
                    ac[3] = fma2(wi2, xb.y, ac[3]);
                }
                if (kc + 8 < HH) {
                    #pragma unroll
                    for (int j = 0; j < 8; ++j) wibuf[j] = winext[j];
                }
            }
            u64t* pg = (u64t*)(pre_x + g * ROWS);
            #pragma unroll
            for (int i = 0; i < 4; ++i) pg[i] = ac[i];
        }

        __syncthreads();  // B: pre_x / pre_h ready; x_s free for refill

        if (t + 1 < TT) {
            const float* xt = x + (size_t)(t + 1) * BB * HH + b0 * HH;
            for (int j = tid; j < HH * ROWS; j += NTHREADS) {
                int r = j >> 7;
                int i = j & (HH - 1);
                x_s[i * ROWS + r] = xt[j];
            }
        }

        // Gate combine + h update (1024 items over 768 threads).
        for (int m = tid; m < HH * ROWS; m += NTHREADS) {
            int i  = m >> 3;
            int rr = m & 7;
            float axr = pre_x[i * ROWS + rr];
            float ahr = pre_h[i * ROWS + rr];
            float axz = pre_x[(HH + i) * ROWS + rr];
            float ahz = pre_h[(HH + i) * ROWS + rr];
            float xn  = pre_x[(2 * HH + i) * ROWS + rr];
            float hn  = pre_h[(2 * HH + i) * ROWS + rr];
            float rg = sigmoid_t(axr + ahr);
            float zg = sigmoid_t(axz + ahz);
            float nn = tanh_ptx(fmaf(rg, hn, xn));
            float hv = h_s[i * ROWS + rr];
            h_s[i * ROWS + rr] = fmaf(zg, hv - nn, nn);   // (1-z)*n + z*h
        }
    }

    __syncthreads();

    // Output projection: out[b] = h[b] . w_out + b_out (one warp per row)
    int warp = tid >> 5;
    int lane = tid & 31;
    if (warp < ROWS) {
        float s = 0.0f;
        for (int i = lane; i < HH; i += 32) s += h_s[i * ROWS + warp] * w_out[i];
        #pragma unroll
        for (int o = 16; o > 0; o >>= 1) s += __shfl_down_sync(0xffffffffu, s, o);
        if (lane == 0) out[b0 + warp] = s + b_out[0];
    }
}

extern "C" void kernel_launch(void* const* d_in, const int* in_sizes, int n_in,
                              void* d_out, int out_size) {
    const float* x    = (const float*)d_in[0];
    const float* h0   = (const float*)d_in[1];
    const float* wih  = (const float*)d_in[2];
    const float* whh  = (const float*)d_in[3];
    const float* bih  = (const float*)d_in[4];
    const float* bhh  = (const float*)d_in[5];
    const float* wout = (const float*)d_in[6];
    const float* bout = (const float*)d_in[7];
    float* out = (float*)d_out;

    cudaFuncSetAttribute(gru_persistent_kernel,
                         cudaFuncAttributeMaxDynamicSharedMemorySize, SMEM_BYTES);

    transpose_weights_kernel<<<(GG * HH + 255) / 256, 256>>>(wih, whh);
    gru_persistent_kernel<<<NBLOCKS, NTHREADS, SMEM_BYTES>>>(
        x, h0, bih, bhh, wout, bout, out);
}